// round 1
// baseline (speedup 1.0000x reference)
#include <cuda_runtime.h>

#define HID 128
#define NUM_R 6
#define N_DSTC 50000
#define KNEIGH (NUM_R * HID)   /* 768 */
#define KTOT (HID + KNEIGH)    /* 896 */

// Scratch (static __device__ — no allocations allowed)
__device__ float g_A[(size_t)N_DSTC * KNEIGH];   // [d][r*128+j] aggregated src feats
__device__ float g_cnt[N_DSTC];                  // edge count per dst
__device__ float g_WT[KTOT * HID];               // folded weights, [k][n] row-major

// ---------------------------------------------------------------- zero scratch
__global__ void zero_kernel() {
    size_t stride = (size_t)gridDim.x * blockDim.x;
    size_t i = (size_t)blockIdx.x * blockDim.x + threadIdx.x;
    float4 z = make_float4(0.f, 0.f, 0.f, 0.f);
    float4* p = reinterpret_cast<float4*>(g_A);
    size_t n4 = (size_t)N_DSTC * KNEIGH / 4;
    for (size_t j = i; j < n4; j += stride) p[j] = z;
    for (size_t j = i; j < (size_t)N_DSTC; j += stride) g_cnt[j] = 0.f;
}

// ------------------------------------------------- fold W_lin into W_r weights
// g_WT[k][n]:
//   k <  128           : W_lin[n][k]                       (dst-feature part)
//   k = 128 + r*128+jj : sum_t W_lin[n][128+t] * W_r[r][t][jj]   (M_r[n][jj])
__global__ void fold_kernel(const float* __restrict__ W_r,
                            const float* __restrict__ W_lin) {
    int k = blockIdx.x;
    int n = threadIdx.x;
    if (k < HID) {
        g_WT[k * HID + n] = W_lin[n * (2 * HID) + k];
    } else {
        int kk = k - HID;
        int r  = kk >> 7;
        int jj = kk & (HID - 1);
        const float* wr = W_r + (size_t)r * HID * HID + jj;   // W_r[r][t][jj], stride HID
        const float* wl = W_lin + n * (2 * HID) + HID;        // W_lin[n][128+t]
        float s = 0.f;
        #pragma unroll 8
        for (int t = 0; t < HID; t++)
            s = fmaf(wl[t], wr[(size_t)t * HID], s);
        g_WT[k * HID + n] = s;
    }
}

// -------------------------------------------------------- per-edge scatter-add
// One warp per edge: gather src row (32 x float4), atomicAdd into A[d][r][*].
__global__ void scatter_kernel(const float* __restrict__ src,
                               const int* __restrict__ es,
                               const int* __restrict__ ed,
                               const int* __restrict__ rt,
                               int E) {
    int lane   = threadIdx.x & 31;
    int warp   = (blockIdx.x * blockDim.x + threadIdx.x) >> 5;
    int nwarps = (gridDim.x * blockDim.x) >> 5;
    for (int e = warp; e < E; e += nwarps) {
        int s = es[e], d = ed[e], r = rt[e];
        float4 v = reinterpret_cast<const float4*>(src + (size_t)s * HID)[lane];
        float* ap = g_A + (size_t)d * KNEIGH + r * HID + lane * 4;
        atomicAdd(ap + 0, v.x);
        atomicAdd(ap + 1, v.y);
        atomicAdd(ap + 2, v.z);
        atomicAdd(ap + 3, v.w);
        if (lane == 0) atomicAdd(&g_cnt[d], 1.f);
    }
}

// ---------------------------------------------- fused GEMM + scale + bias+ReLU
// out[d][n] = relu( sum_{k<128} dst[d][k]*WT[k][n]
//                 + (1/max(cnt,1)) * sum_{k'} A[d][k']*WT[128+k'][n] + b[n] )
#define BM 128
#define BN 64
#define BK 16

__global__ __launch_bounds__(256) void gemm_kernel(const float* __restrict__ dstf,
                                                   const float* __restrict__ b_lin,
                                                   float* __restrict__ out,
                                                   int n_dst) {
    __shared__ float As[BK][BM + 4];
    __shared__ float Bs[BK][BN];
    int tid = threadIdx.x;
    int tx = tid & 15;   // 16 groups of 4 output cols
    int ty = tid >> 4;   // 16 groups of 8 rows
    int rowTile = blockIdx.x >> 1;
    int colTile = blockIdx.x & 1;    // consecutive blocks share A rows -> L2 reuse
    int rowBase = rowTile * BM;
    int colBase = colTile * BN;

    float acc[8][4];
    #pragma unroll
    for (int i = 0; i < 8; i++)
        #pragma unroll
        for (int j = 0; j < 4; j++) acc[i][j] = 0.f;

    // ---- phase 1: neighbor part over g_A (weight rows HID + kt + k) ----
    for (int kt = 0; kt < KNEIGH; kt += BK) {
        #pragma unroll
        for (int l = 0; l < 2; l++) {
            int idx = tid + l * 256;     // 512 float4 slots: 128 rows x 4
            int r  = idx >> 2;
            int c4 = idx & 3;
            int grow = rowBase + r;
            float4 v = make_float4(0.f, 0.f, 0.f, 0.f);
            if (grow < n_dst)
                v = *reinterpret_cast<const float4*>(g_A + (size_t)grow * KNEIGH + kt + c4 * 4);
            As[c4 * 4 + 0][r] = v.x;
            As[c4 * 4 + 1][r] = v.y;
            As[c4 * 4 + 2][r] = v.z;
            As[c4 * 4 + 3][r] = v.w;
        }
        {
            int k  = tid >> 4;
            int n4 = tid & 15;
            *reinterpret_cast<float4*>(&Bs[k][n4 * 4]) =
                *reinterpret_cast<const float4*>(g_WT + (size_t)(HID + kt + k) * HID + colBase + n4 * 4);
        }
        __syncthreads();
        #pragma unroll
        for (int k = 0; k < BK; k++) {
            float a[8], b[4];
            *reinterpret_cast<float4*>(&a[0]) = *reinterpret_cast<float4*>(&As[k][ty * 8]);
            *reinterpret_cast<float4*>(&a[4]) = *reinterpret_cast<float4*>(&As[k][ty * 8 + 4]);
            *reinterpret_cast<float4*>(&b[0]) = *reinterpret_cast<float4*>(&Bs[k][tx * 4]);
            #pragma unroll
            for (int i = 0; i < 8; i++)
                #pragma unroll
                for (int j = 0; j < 4; j++)
                    acc[i][j] = fmaf(a[i], b[j], acc[i][j]);
        }
        __syncthreads();
    }

    // ---- scale neighbor sum by 1/max(cnt,1) (mean aggregation) ----
    #pragma unroll
    for (int i = 0; i < 8; i++) {
        int grow = rowBase + ty * 8 + i;
        float c = (grow < n_dst) ? g_cnt[grow] : 1.f;
        float inv = 1.f / fmaxf(c, 1.f);
        #pragma unroll
        for (int j = 0; j < 4; j++) acc[i][j] *= inv;
    }

    // ---- phase 2: dst-feature part (weight rows kt + k) ----
    for (int kt = 0; kt < HID; kt += BK) {
        #pragma unroll
        for (int l = 0; l < 2; l++) {
            int idx = tid + l * 256;
            int r  = idx >> 2;
            int c4 = idx & 3;
            int grow = rowBase + r;
            float4 v = make_float4(0.f, 0.f, 0.f, 0.f);
            if (grow < n_dst)
                v = *reinterpret_cast<const float4*>(dstf + (size_t)grow * HID + kt + c4 * 4);
            As[c4 * 4 + 0][r] = v.x;
            As[c4 * 4 + 1][r] = v.y;
            As[c4 * 4 + 2][r] = v.z;
            As[c4 * 4 + 3][r] = v.w;
        }
        {
            int k  = tid >> 4;
            int n4 = tid & 15;
            *reinterpret_cast<float4*>(&Bs[k][n4 * 4]) =
                *reinterpret_cast<const float4*>(g_WT + (size_t)(kt + k) * HID + colBase + n4 * 4);
        }
        __syncthreads();
        #pragma unroll
        for (int k = 0; k < BK; k++) {
            float a[8], b[4];
            *reinterpret_cast<float4*>(&a[0]) = *reinterpret_cast<float4*>(&As[k][ty * 8]);
            *reinterpret_cast<float4*>(&a[4]) = *reinterpret_cast<float4*>(&As[k][ty * 8 + 4]);
            *reinterpret_cast<float4*>(&b[0]) = *reinterpret_cast<float4*>(&Bs[k][tx * 4]);
            #pragma unroll
            for (int i = 0; i < 8; i++)
                #pragma unroll
                for (int j = 0; j < 4; j++)
                    acc[i][j] = fmaf(a[i], b[j], acc[i][j]);
        }
        __syncthreads();
    }

    // ---- epilogue: bias + relu + store ----
    float bb[4];
    *reinterpret_cast<float4*>(bb) =
        *reinterpret_cast<const float4*>(b_lin + colBase + tx * 4);
    #pragma unroll
    for (int i = 0; i < 8; i++) {
        int grow = rowBase + ty * 8 + i;
        if (grow >= n_dst) continue;
        float4 o;
        o.x = fmaxf(acc[i][0] + bb[0], 0.f);
        o.y = fmaxf(acc[i][1] + bb[1], 0.f);
        o.z = fmaxf(acc[i][2] + bb[2], 0.f);
        o.w = fmaxf(acc[i][3] + bb[3], 0.f);
        *reinterpret_cast<float4*>(out + (size_t)grow * HID + colBase + tx * 4) = o;
    }
}

// -----------------------------------------------------------------------------
extern "C" void kernel_launch(void* const* d_in, const int* in_sizes, int n_in,
                              void* d_out, int out_size) {
    const float* src   = (const float*)d_in[0];
    const float* dstf  = (const float*)d_in[1];
    const float* W_r   = (const float*)d_in[2];
    const float* W_lin = (const float*)d_in[3];
    const float* b_lin = (const float*)d_in[4];
    const int*   es    = (const int*)d_in[5];
    const int*   ed    = (const int*)d_in[6];
    const int*   rt    = (const int*)d_in[7];
    float* out = (float*)d_out;

    int E     = in_sizes[5];
    int n_dst = in_sizes[1] / HID;

    zero_kernel<<<4096, 256>>>();
    fold_kernel<<<KTOT, HID>>>(W_r, W_lin);
    scatter_kernel<<<2048, 256>>>(src, es, ed, rt, E);

    int rowTiles = (n_dst + BM - 1) / BM;
    gemm_kernel<<<rowTiles * 2, 256>>>(dstf, b_lin, out, n_dst);
}

// round 2
// speedup vs baseline: 1.9476x; 1.9476x over previous
#include <cuda_runtime.h>
#include <cuda_bf16.h>
#include <cstdint>

#define HID 128
#define NUM_R 6
#define N_DSTC 50000
#define KNEIGH (NUM_R * HID)   /* 768 */
#define KTOT (HID + KNEIGH)    /* 896 */

// Scratch (static __device__ — no allocations allowed)
__device__ float g_A[(size_t)N_DSTC * KNEIGH];       // aggregated src feats per (dst, rating)
__device__ float g_cnt[N_DSTC];                      // edge count per dst
__device__ __nv_bfloat16 g_WTh[KTOT * HID];          // folded weights, bf16 high part
__device__ __nv_bfloat16 g_WTl[KTOT * HID];          // folded weights, bf16 low part

// ---------------------------------------------------------------- zero scratch
__global__ void zero_kernel() {
    size_t stride = (size_t)gridDim.x * blockDim.x;
    size_t i = (size_t)blockIdx.x * blockDim.x + threadIdx.x;
    float4 z = make_float4(0.f, 0.f, 0.f, 0.f);
    float4* p = reinterpret_cast<float4*>(g_A);
    size_t n4 = (size_t)N_DSTC * KNEIGH / 4;
    for (size_t j = i; j < n4; j += stride) p[j] = z;
    for (size_t j = i; j < (size_t)N_DSTC; j += stride) g_cnt[j] = 0.f;
}

// ------------------------------------------------- fold W_lin into W_r weights
// WT[k][n] (fp32, then split to bf16 hi/lo):
//   k <  128           : W_lin[n][k]
//   k = 128 + r*128+jj : sum_t W_lin[n][128+t] * W_r[r][t][jj]
__global__ void fold_kernel(const float* __restrict__ W_r,
                            const float* __restrict__ W_lin) {
    int k = blockIdx.x;
    int n = threadIdx.x;
    float s;
    if (k < HID) {
        s = W_lin[n * (2 * HID) + k];
    } else {
        int kk = k - HID;
        int r  = kk >> 7;
        int jj = kk & (HID - 1);
        const float* wr = W_r + (size_t)r * HID * HID + jj;
        const float* wl = W_lin + n * (2 * HID) + HID;
        s = 0.f;
        #pragma unroll 8
        for (int t = 0; t < HID; t++)
            s = fmaf(wl[t], wr[(size_t)t * HID], s);
    }
    __nv_bfloat16 h = __float2bfloat16(s);
    __nv_bfloat16 l = __float2bfloat16(s - __bfloat162float(h));
    g_WTh[k * HID + n] = h;
    g_WTl[k * HID + n] = l;
}

// -------------------------------------------------------- per-edge scatter-add
// One warp per edge: gather src row (32 x float4), vector-red into A[d][r][*].
__global__ void scatter_kernel(const float* __restrict__ src,
                               const int* __restrict__ es,
                               const int* __restrict__ ed,
                               const int* __restrict__ rt,
                               int E) {
    int lane   = threadIdx.x & 31;
    int warp   = (blockIdx.x * blockDim.x + threadIdx.x) >> 5;
    int nwarps = (gridDim.x * blockDim.x) >> 5;
    for (int e = warp; e < E; e += nwarps) {
        int s = es[e], d = ed[e], r = rt[e];
        float4 v = reinterpret_cast<const float4*>(src + (size_t)s * HID)[lane];
        float* ap = g_A + (size_t)d * KNEIGH + r * HID + lane * 4;
        asm volatile("red.global.add.v4.f32 [%0], {%1,%2,%3,%4};"
                     :: "l"(ap), "f"(v.x), "f"(v.y), "f"(v.z), "f"(v.w) : "memory");
        if (lane == 0)
            asm volatile("red.global.add.f32 [%0], %1;"
                         :: "l"(&g_cnt[d]), "f"(1.0f) : "memory");
    }
}

// ---------------------------------------------- fused tensor-core GEMM
// out[d][n] = relu( dst-part + (1/max(cnt,1))*neigh-part + b[n] )
// Split-precision bf16: X = Xh + Xl, W = Wh + Wl; acc = Xh*Wh + Xh*Wl + Xl*Wh.
#define BM 128
#define BN 64
#define BK 32
#define AS_STRIDE 40   /* 32 + 8 pad bf16 (conflict-free ldmatrix) */
#define BS_STRIDE 72   /* 64 + 8 pad bf16 (conflict-free ldmatrix.trans) */

__device__ __forceinline__ uint32_t smaddr(const void* p) {
    return (uint32_t)__cvta_generic_to_shared(p);
}
__device__ __forceinline__ void ldm_x4(uint32_t& d0, uint32_t& d1, uint32_t& d2, uint32_t& d3, uint32_t a) {
    asm volatile("ldmatrix.sync.aligned.m8n8.x4.shared.b16 {%0,%1,%2,%3}, [%4];"
                 : "=r"(d0), "=r"(d1), "=r"(d2), "=r"(d3) : "r"(a));
}
__device__ __forceinline__ void ldm_x4t(uint32_t& d0, uint32_t& d1, uint32_t& d2, uint32_t& d3, uint32_t a) {
    asm volatile("ldmatrix.sync.aligned.m8n8.x4.trans.shared.b16 {%0,%1,%2,%3}, [%4];"
                 : "=r"(d0), "=r"(d1), "=r"(d2), "=r"(d3) : "r"(a));
}
__device__ __forceinline__ void mma16816(float* c, const uint32_t* a, const uint32_t* b) {
    asm volatile("mma.sync.aligned.m16n8k16.row.col.f32.bf16.bf16.f32 "
                 "{%0,%1,%2,%3}, {%4,%5,%6,%7}, {%8,%9}, {%0,%1,%2,%3};"
                 : "+f"(c[0]), "+f"(c[1]), "+f"(c[2]), "+f"(c[3])
                 : "r"(a[0]), "r"(a[1]), "r"(a[2]), "r"(a[3]), "r"(b[0]), "r"(b[1]));
}

__global__ __launch_bounds__(256) void gemm_kernel(const float* __restrict__ dstf,
                                                   const float* __restrict__ b_lin,
                                                   float* __restrict__ out,
                                                   int n_dst) {
    __shared__ __nv_bfloat16 As_h[BM * AS_STRIDE];
    __shared__ __nv_bfloat16 As_l[BM * AS_STRIDE];
    __shared__ __nv_bfloat16 Bs_h[BK * BS_STRIDE];
    __shared__ __nv_bfloat16 Bs_l[BK * BS_STRIDE];

    int tid  = threadIdx.x;
    int lane = tid & 31;
    int warp = tid >> 5;
    int wm = warp >> 1;          // 0..3, each 32 rows
    int wn = warp & 1;           // 0..1, each 32 cols
    int rowBase = (blockIdx.x >> 1) * BM;
    int colBase = (blockIdx.x & 1) * BN;

    float acc[2][4][4];          // [tm(16)][tn(8)][frag]
    #pragma unroll
    for (int i = 0; i < 2; i++)
        #pragma unroll
        for (int j = 0; j < 4; j++)
            #pragma unroll
            for (int q = 0; q < 4; q++) acc[i][j][q] = 0.f;

    // precompute ldmatrix smem addresses (offsets change per kk)
    int aRow = wm * 32 + (lane & 15);                    // + tm*16
    int aColSel = (lane >> 4) * 8;                       // + kk
    int bRowSel = (lane & 15);                           // + kk
    int bCol = wn * 32 + (lane >> 4) * 8;                // + half*16

    #pragma unroll 1
    for (int phase = 0; phase < 2; phase++) {
        const float* Asrc = (phase == 0) ? g_A : dstf;
        int strideA = (phase == 0) ? KNEIGH : HID;
        int Kp      = (phase == 0) ? KNEIGH : HID;
        int wrow0   = (phase == 0) ? HID : 0;

        #pragma unroll 1
        for (int kt = 0; kt < Kp; kt += BK) {
            // ---- load & split A tile: 128 x 32 fp32 -> bf16 hi/lo ----
            #pragma unroll
            for (int i = 0; i < 4; i++) {
                int f = tid + i * 256;       // 0..1023
                int r  = f >> 3;
                int c4 = f & 7;
                int grow = rowBase + r;
                float4 v = make_float4(0.f, 0.f, 0.f, 0.f);
                if (grow < n_dst)
                    v = *reinterpret_cast<const float4*>(Asrc + (size_t)grow * strideA + kt + c4 * 4);
                __nv_bfloat162 h01 = __floats2bfloat162_rn(v.x, v.y);
                __nv_bfloat162 h23 = __floats2bfloat162_rn(v.z, v.w);
                __nv_bfloat162 l01 = __floats2bfloat162_rn(v.x - __low2float(h01), v.y - __high2float(h01));
                __nv_bfloat162 l23 = __floats2bfloat162_rn(v.z - __low2float(h23), v.w - __high2float(h23));
                __nv_bfloat162* ph = reinterpret_cast<__nv_bfloat162*>(&As_h[r * AS_STRIDE + c4 * 4]);
                __nv_bfloat162* pl = reinterpret_cast<__nv_bfloat162*>(&As_l[r * AS_STRIDE + c4 * 4]);
                ph[0] = h01; ph[1] = h23;
                pl[0] = l01; pl[1] = l23;
            }
            // ---- load B tile: 32 x 64 bf16 (hi and lo) ----
            {
                int r = tid >> 3;
                int seg = tid & 7;
                size_t go = (size_t)(wrow0 + kt + r) * HID + colBase + seg * 8;
                *reinterpret_cast<uint4*>(&Bs_h[r * BS_STRIDE + seg * 8]) =
                    *reinterpret_cast<const uint4*>(&g_WTh[go]);
                *reinterpret_cast<uint4*>(&Bs_l[r * BS_STRIDE + seg * 8]) =
                    *reinterpret_cast<const uint4*>(&g_WTl[go]);
            }
            __syncthreads();

            #pragma unroll
            for (int kk = 0; kk < BK; kk += 16) {
                uint32_t ah[2][4], al[2][4];
                #pragma unroll
                for (int tm = 0; tm < 2; tm++) {
                    uint32_t addr_h = smaddr(&As_h[(aRow + tm * 16) * AS_STRIDE + kk + aColSel]);
                    ldm_x4(ah[tm][0], ah[tm][1], ah[tm][2], ah[tm][3], addr_h);
                    uint32_t addr_l = smaddr(&As_l[(aRow + tm * 16) * AS_STRIDE + kk + aColSel]);
                    ldm_x4(al[tm][0], al[tm][1], al[tm][2], al[tm][3], addr_l);
                }
                uint32_t bh[4][2], bl[4][2];
                #pragma unroll
                for (int half = 0; half < 2; half++) {
                    uint32_t r0, r1, r2, r3;
                    uint32_t addr_h = smaddr(&Bs_h[(kk + bRowSel) * BS_STRIDE + bCol + half * 16]);
                    ldm_x4t(r0, r1, r2, r3, addr_h);
                    bh[half * 2 + 0][0] = r0; bh[half * 2 + 0][1] = r1;
                    bh[half * 2 + 1][0] = r2; bh[half * 2 + 1][1] = r3;
                    uint32_t addr_l = smaddr(&Bs_l[(kk + bRowSel) * BS_STRIDE + bCol + half * 16]);
                    ldm_x4t(r0, r1, r2, r3, addr_l);
                    bl[half * 2 + 0][0] = r0; bl[half * 2 + 0][1] = r1;
                    bl[half * 2 + 1][0] = r2; bl[half * 2 + 1][1] = r3;
                }
                #pragma unroll
                for (int tm = 0; tm < 2; tm++)
                    #pragma unroll
                    for (int tn = 0; tn < 4; tn++) {
                        mma16816(acc[tm][tn], ah[tm], bh[tn]);
                        mma16816(acc[tm][tn], ah[tm], bl[tn]);
                        mma16816(acc[tm][tn], al[tm], bh[tn]);
                    }
            }
            __syncthreads();
        }

        if (phase == 0) {
            // scale neighbor sum by 1/max(cnt,1)
            #pragma unroll
            for (int tm = 0; tm < 2; tm++) {
                int r0 = rowBase + wm * 32 + tm * 16 + (lane >> 2);
                int r1 = r0 + 8;
                float c0 = (r0 < n_dst) ? g_cnt[r0] : 1.f;
                float c1 = (r1 < n_dst) ? g_cnt[r1] : 1.f;
                float i0 = 1.f / fmaxf(c0, 1.f);
                float i1 = 1.f / fmaxf(c1, 1.f);
                #pragma unroll
                for (int tn = 0; tn < 4; tn++) {
                    acc[tm][tn][0] *= i0; acc[tm][tn][1] *= i0;
                    acc[tm][tn][2] *= i1; acc[tm][tn][3] *= i1;
                }
            }
        }
    }

    // ---- epilogue: bias + relu + store (float2 per row-pair) ----
    #pragma unroll
    for (int tn = 0; tn < 4; tn++) {
        int col = colBase + wn * 32 + tn * 8 + 2 * (lane & 3);
        float b0 = b_lin[col];
        float b1 = b_lin[col + 1];
        #pragma unroll
        for (int tm = 0; tm < 2; tm++) {
            int r0 = rowBase + wm * 32 + tm * 16 + (lane >> 2);
            int r1 = r0 + 8;
            if (r0 < n_dst) {
                float2 o;
                o.x = fmaxf(acc[tm][tn][0] + b0, 0.f);
                o.y = fmaxf(acc[tm][tn][1] + b1, 0.f);
                *reinterpret_cast<float2*>(out + (size_t)r0 * HID + col) = o;
            }
            if (r1 < n_dst) {
                float2 o;
                o.x = fmaxf(acc[tm][tn][2] + b0, 0.f);
                o.y = fmaxf(acc[tm][tn][3] + b1, 0.f);
                *reinterpret_cast<float2*>(out + (size_t)r1 * HID + col) = o;
            }
        }
    }
}

// -----------------------------------------------------------------------------
extern "C" void kernel_launch(void* const* d_in, const int* in_sizes, int n_in,
                              void* d_out, int out_size) {
    const float* src   = (const float*)d_in[0];
    const float* dstf  = (const float*)d_in[1];
    const float* W_r   = (const float*)d_in[2];
    const float* W_lin = (const float*)d_in[3];
    const float* b_lin = (const float*)d_in[4];
    const int*   es    = (const int*)d_in[5];
    const int*   ed    = (const int*)d_in[6];
    const int*   rt    = (const int*)d_in[7];
    float* out = (float*)d_out;

    int E     = in_sizes[5];
    int n_dst = in_sizes[1] / HID;

    zero_kernel<<<4096, 256>>>();
    fold_kernel<<<KTOT, HID>>>(W_r, W_lin);
    scatter_kernel<<<2048, 256>>>(src, es, ed, rt, E);

    int rowTiles = (n_dst + BM - 1) / BM;
    gemm_kernel<<<rowTiles * 2, 256>>>(dstf, b_lin, out, n_dst);
}

// round 5
// speedup vs baseline: 2.3332x; 1.1980x over previous
#include <cuda_runtime.h>
#include <cuda_bf16.h>
#include <cstdint>

#define HID 128
#define NUM_R 6
#define N_MAXN 50048                 /* padded capacity */
#define KY 768                       /* NUM_R * HID */

// ---- static scratch (device-code access ONLY — never passed from host) ----
__device__ float g_Y[(size_t)N_MAXN * KY];            // transformed src feats [s][r*128+j]
__device__ float g_A2[(size_t)N_MAXN * HID];          // aggregated neighbor sums per dst
__device__ float g_cnt[N_MAXN];
__device__ __nv_bfloat16 g_WYh[HID * KY];             // WY[t][r*128+j] = W_r[r][j][t]
__device__ __nv_bfloat16 g_WYl[HID * KY];
__device__ __nv_bfloat16 g_WZh[256 * HID];            // WZ[k][n] = W_lin[n][k]
__device__ __nv_bfloat16 g_WZl[256 * HID];

// ---------------------------------------------------------------- helpers
__device__ __forceinline__ uint32_t smaddr(const void* p) {
    return (uint32_t)__cvta_generic_to_shared(p);
}
__device__ __forceinline__ void ldm_x4(uint32_t& d0, uint32_t& d1, uint32_t& d2, uint32_t& d3, uint32_t a) {
    asm volatile("ldmatrix.sync.aligned.m8n8.x4.shared.b16 {%0,%1,%2,%3}, [%4];"
                 : "=r"(d0), "=r"(d1), "=r"(d2), "=r"(d3) : "r"(a));
}
__device__ __forceinline__ void ldm_x4t(uint32_t& d0, uint32_t& d1, uint32_t& d2, uint32_t& d3, uint32_t a) {
    asm volatile("ldmatrix.sync.aligned.m8n8.x4.trans.shared.b16 {%0,%1,%2,%3}, [%4];"
                 : "=r"(d0), "=r"(d1), "=r"(d2), "=r"(d3) : "r"(a));
}
__device__ __forceinline__ void mma16816(float* c, const uint32_t* a, const uint32_t* b) {
    asm volatile("mma.sync.aligned.m16n8k16.row.col.f32.bf16.bf16.f32 "
                 "{%0,%1,%2,%3}, {%4,%5,%6,%7}, {%8,%9}, {%0,%1,%2,%3};"
                 : "+f"(c[0]), "+f"(c[1]), "+f"(c[2]), "+f"(c[3])
                 : "r"(a[0]), "r"(a[1]), "r"(a[2]), "r"(a[3]), "r"(b[0]), "r"(b[1]));
}
__device__ __forceinline__ void split2(float v, __nv_bfloat16& h, __nv_bfloat16& l) {
    h = __float2bfloat16(v);
    l = __float2bfloat16(v - __bfloat162float(h));
}

// ---------------------------------------------------------------- zero
__global__ void zero_kernel(int n_dst) {
    size_t stride = (size_t)gridDim.x * blockDim.x;
    size_t i = (size_t)blockIdx.x * blockDim.x + threadIdx.x;
    size_t n4 = (size_t)n_dst * HID / 4;
    float4 z = make_float4(0.f, 0.f, 0.f, 0.f);
    float4* p = reinterpret_cast<float4*>(g_A2);
    for (size_t j = i; j < n4; j += stride) p[j] = z;
    for (size_t j = i; j < (size_t)n_dst; j += stride) g_cnt[j] = 0.f;
}

// ------------------------------------------------- weight transposes (tiny)
__global__ void prep_w_kernel(const float* __restrict__ W_r,
                              const float* __restrict__ W_lin) {
    int stride = gridDim.x * blockDim.x;
    int i = blockIdx.x * blockDim.x + threadIdx.x;
    for (int j = i; j < HID * KY; j += stride) {         // WY[t][col]
        int t = j / KY, col = j % KY;
        int r = col >> 7, jj = col & 127;
        float w = W_r[((size_t)r * HID + jj) * HID + t];
        __nv_bfloat16 h, l; split2(w, h, l);
        g_WYh[j] = h; g_WYl[j] = l;
    }
    for (int j = i; j < 256 * HID; j += stride) {        // WZ[k][n]
        int k = j >> 7, n = j & 127;
        float w = W_lin[n * 256 + k];
        __nv_bfloat16 h, l; split2(w, h, l);
        g_WZh[j] = h; g_WZl[j] = l;
    }
}

// ---------------------------------------------- split-bf16 tensor-core GEMM
// Round-2 proven internals: BK=32, in-loop fp32->bf16 hi/lo split of A,
// 3-term mma (Ah*Bh + Ah*Bl + Al*Bh), fp32 accum.
// MODE 0: Y = Ap(src) @ WY        -> g_Y   (single phase, no bias/relu)
// MODE 1: out = relu((A2@WZ[128:])/cnt + Ap(dstf)@WZ[0:128] + bias)
#define BM 128
#define BN 64
#define BK 32
#define AS_STRIDE 40   /* 32 + 8 pad bf16 */
#define BS_STRIDE 72   /* 64 + 8 pad bf16 */

template <int MODE>
__global__ __launch_bounds__(256) void gemm_kernel(
    const float* __restrict__ Ap, const float* __restrict__ bias,
    float* __restrict__ outParam, int M, int colTiles) {

    constexpr bool TWO_PHASE = (MODE == 1);
    constexpr bool EPI = (MODE == 1);
    constexpr int LDB = (MODE == 0) ? KY : HID;
    constexpr int LDO = (MODE == 0) ? KY : HID;

    // scratch globals resolved in DEVICE code (host must not pass them)
    const __nv_bfloat16* __restrict__ Bh = (MODE == 0) ? g_WYh : g_WZh;
    const __nv_bfloat16* __restrict__ Bl = (MODE == 0) ? g_WYl : g_WZl;
    float* __restrict__ out = (MODE == 0) ? g_Y : outParam;

    __shared__ __nv_bfloat16 As_h[BM * AS_STRIDE];
    __shared__ __nv_bfloat16 As_l[BM * AS_STRIDE];
    __shared__ __nv_bfloat16 Bs_h[BK * BS_STRIDE];
    __shared__ __nv_bfloat16 Bs_l[BK * BS_STRIDE];

    int tid  = threadIdx.x;
    int lane = tid & 31;
    int warp = tid >> 5;
    int wm = warp >> 1;          // 0..3, each 32 rows
    int wn = warp & 1;           // 0..1, each 32 cols
    int rowBase = (blockIdx.x / colTiles) * BM;
    int colBase = (blockIdx.x % colTiles) * BN;

    float acc[2][4][4];
    #pragma unroll
    for (int i = 0; i < 2; i++)
        #pragma unroll
        for (int j = 0; j < 4; j++)
            #pragma unroll
            for (int q = 0; q < 4; q++) acc[i][j][q] = 0.f;

    int aRow = wm * 32 + (lane & 15);
    int aColSel = (lane >> 4) * 8;
    int bRowSel = (lane & 15);
    int bCol = wn * 32 + (lane >> 4) * 8;

    constexpr int nPhase = TWO_PHASE ? 2 : 1;

    #pragma unroll 1
    for (int phase = 0; phase < nPhase; phase++) {
        // phase 0 of MODE 1 runs over g_A2 (neighbor sums, weight rows 128..255);
        // phase 1 (or MODE 0's only phase) runs over Ap.
        const float* Asrc = (TWO_PHASE && phase == 0) ? g_A2 : Ap;
        int wrow0 = (TWO_PHASE && phase == 0) ? HID : 0;

        #pragma unroll 1
        for (int kt = 0; kt < HID; kt += BK) {
            // ---- load & split A tile: 128 x 32 fp32 -> bf16 hi/lo ----
            #pragma unroll
            for (int i = 0; i < 4; i++) {
                int f = tid + i * 256;       // 0..1023
                int r  = f >> 3;
                int c4 = f & 7;
                int grow = rowBase + r;
                float4 v = make_float4(0.f, 0.f, 0.f, 0.f);
                if (grow < M)
                    v = *reinterpret_cast<const float4*>(Asrc + (size_t)grow * HID + kt + c4 * 4);
                __nv_bfloat162 h01 = __floats2bfloat162_rn(v.x, v.y);
                __nv_bfloat162 h23 = __floats2bfloat162_rn(v.z, v.w);
                __nv_bfloat162 l01 = __floats2bfloat162_rn(v.x - __low2float(h01), v.y - __high2float(h01));
                __nv_bfloat162 l23 = __floats2bfloat162_rn(v.z - __low2float(h23), v.w - __high2float(h23));
                __nv_bfloat162* ph = reinterpret_cast<__nv_bfloat162*>(&As_h[r * AS_STRIDE + c4 * 4]);
                __nv_bfloat162* pl = reinterpret_cast<__nv_bfloat162*>(&As_l[r * AS_STRIDE + c4 * 4]);
                ph[0] = h01; ph[1] = h23;
                pl[0] = l01; pl[1] = l23;
            }
            // ---- load B tile: 32 x 64 bf16 (hi and lo) ----
            {
                int r = tid >> 3;
                int seg = tid & 7;
                size_t go = (size_t)(wrow0 + kt + r) * LDB + colBase + seg * 8;
                *reinterpret_cast<uint4*>(&Bs_h[r * BS_STRIDE + seg * 8]) =
                    *reinterpret_cast<const uint4*>(&Bh[go]);
                *reinterpret_cast<uint4*>(&Bs_l[r * BS_STRIDE + seg * 8]) =
                    *reinterpret_cast<const uint4*>(&Bl[go]);
            }
            __syncthreads();

            #pragma unroll
            for (int kk = 0; kk < BK; kk += 16) {
                uint32_t ah[2][4], al[2][4];
                #pragma unroll
                for (int tm = 0; tm < 2; tm++) {
                    uint32_t addr_h = smaddr(&As_h[(aRow + tm * 16) * AS_STRIDE + kk + aColSel]);
                    ldm_x4(ah[tm][0], ah[tm][1], ah[tm][2], ah[tm][3], addr_h);
                    uint32_t addr_l = smaddr(&As_l[(aRow + tm * 16) * AS_STRIDE + kk + aColSel]);
                    ldm_x4(al[tm][0], al[tm][1], al[tm][2], al[tm][3], addr_l);
                }
                uint32_t bh[4][2], bl[4][2];
                #pragma unroll
                for (int half = 0; half < 2; half++) {
                    uint32_t r0, r1, r2, r3;
                    uint32_t addr_h = smaddr(&Bs_h[(kk + bRowSel) * BS_STRIDE + bCol + half * 16]);
                    ldm_x4t(r0, r1, r2, r3, addr_h);
                    bh[half * 2 + 0][0] = r0; bh[half * 2 + 0][1] = r1;
                    bh[half * 2 + 1][0] = r2; bh[half * 2 + 1][1] = r3;
                    uint32_t addr_l = smaddr(&Bs_l[(kk + bRowSel) * BS_STRIDE + bCol + half * 16]);
                    ldm_x4t(r0, r1, r2, r3, addr_l);
                    bl[half * 2 + 0][0] = r0; bl[half * 2 + 0][1] = r1;
                    bl[half * 2 + 1][0] = r2; bl[half * 2 + 1][1] = r3;
                }
                #pragma unroll
                for (int tm = 0; tm < 2; tm++)
                    #pragma unroll
                    for (int tn = 0; tn < 4; tn++) {
                        mma16816(acc[tm][tn], ah[tm], bh[tn]);
                        mma16816(acc[tm][tn], ah[tm], bl[tn]);
                        mma16816(acc[tm][tn], al[tm], bh[tn]);
                    }
            }
            __syncthreads();
        }

        if (TWO_PHASE && phase == 0) {
            // scale neighbor sum by 1/max(cnt,1)
            #pragma unroll
            for (int tm = 0; tm < 2; tm++) {
                int r0 = rowBase + wm * 32 + tm * 16 + (lane >> 2);
                int r1 = r0 + 8;
                float c0 = (r0 < M) ? g_cnt[r0] : 1.f;
                float c1 = (r1 < M) ? g_cnt[r1] : 1.f;
                float i0 = 1.f / fmaxf(c0, 1.f);
                float i1 = 1.f / fmaxf(c1, 1.f);
                #pragma unroll
                for (int tn = 0; tn < 4; tn++) {
                    acc[tm][tn][0] *= i0; acc[tm][tn][1] *= i0;
                    acc[tm][tn][2] *= i1; acc[tm][tn][3] *= i1;
                }
            }
        }
    }

    // ---- epilogue ----
    #pragma unroll
    for (int tn = 0; tn < 4; tn++) {
        int col = colBase + wn * 32 + tn * 8 + 2 * (lane & 3);
        float b0 = 0.f, b1 = 0.f;
        if (EPI) { b0 = bias[col]; b1 = bias[col + 1]; }
        #pragma unroll
        for (int tm = 0; tm < 2; tm++) {
            int r0 = rowBase + wm * 32 + tm * 16 + (lane >> 2);
            int r1 = r0 + 8;
            if (r0 < M) {
                float2 o;
                if (EPI) { o.x = fmaxf(acc[tm][tn][0] + b0, 0.f); o.y = fmaxf(acc[tm][tn][1] + b1, 0.f); }
                else     { o.x = acc[tm][tn][0];                  o.y = acc[tm][tn][1]; }
                *reinterpret_cast<float2*>(out + (size_t)r0 * LDO + col) = o;
            }
            if (r1 < M) {
                float2 o;
                if (EPI) { o.x = fmaxf(acc[tm][tn][2] + b0, 0.f); o.y = fmaxf(acc[tm][tn][3] + b1, 0.f); }
                else     { o.x = acc[tm][tn][2];                  o.y = acc[tm][tn][3]; }
                *reinterpret_cast<float2*>(out + (size_t)r1 * LDO + col) = o;
            }
        }
    }
}

// -------------------------------------------------------- per-edge scatter-add
// Gather Y[src_e, rating_e*128 ..] row, red.v4 into A2[dst_e] (L2-resident).
__global__ void scatter_kernel(const int* __restrict__ es,
                               const int* __restrict__ ed,
                               const int* __restrict__ rt,
                               int E) {
    int lane   = threadIdx.x & 31;
    int warp   = (blockIdx.x * blockDim.x + threadIdx.x) >> 5;
    int nwarps = (gridDim.x * blockDim.x) >> 5;
    for (int e = warp; e < E; e += nwarps) {
        int s = es[e], d = ed[e], r = rt[e];
        float4 v = reinterpret_cast<const float4*>(g_Y + (size_t)s * KY + r * HID)[lane];
        float* ap = g_A2 + (size_t)d * HID + lane * 4;
        asm volatile("red.global.add.v4.f32 [%0], {%1,%2,%3,%4};"
                     :: "l"(ap), "f"(v.x), "f"(v.y), "f"(v.z), "f"(v.w) : "memory");
        if (lane == 0)
            asm volatile("red.global.add.f32 [%0], %1;"
                         :: "l"(&g_cnt[d]), "f"(1.0f) : "memory");
    }
}

// -----------------------------------------------------------------------------
extern "C" void kernel_launch(void* const* d_in, const int* in_sizes, int n_in,
                              void* d_out, int out_size) {
    const float* src   = (const float*)d_in[0];
    const float* dstf  = (const float*)d_in[1];
    const float* W_r   = (const float*)d_in[2];
    const float* W_lin = (const float*)d_in[3];
    const float* b_lin = (const float*)d_in[4];
    const int*   es    = (const int*)d_in[5];
    const int*   ed    = (const int*)d_in[6];
    const int*   rt    = (const int*)d_in[7];
    float* out = (float*)d_out;

    int E     = in_sizes[5];
    int n_src = in_sizes[0] / HID;
    int n_dst = in_sizes[1] / HID;

    zero_kernel<<<1024, 256>>>(n_dst);
    prep_w_kernel<<<384, 256>>>(W_r, W_lin);

    // Y = src @ WY  : [n_src, 768], K=128  (writes g_Y internally)
    int rowTilesY = (n_src + BM - 1) / BM;
    gemm_kernel<0><<<rowTilesY * (KY / BN), 256>>>(src, nullptr, nullptr, n_src, KY / BN);

    scatter_kernel<<<2048, 256>>>(es, ed, rt, E);

    // out = relu( (A2/cnt) @ WZ[128:256] + dstf @ WZ[0:128] + b )
    int rowTilesF = (n_dst + BM - 1) / BM;
    gemm_kernel<1><<<rowTilesF * (HID / BN), 256>>>(dstf, b_lin, out, n_dst, HID / BN);
}